// round 6
// baseline (speedup 1.0000x reference)
#include <cuda_runtime.h>
#include <stdint.h>
#include <math.h>

#define BATCH 256
#define SEQ   256
#define IDIM  128
#define HID   1024
#define KEFF  1152
#define OUTC  10

#define NCTA   128
#define NTH    256
#define NCHK   18            // chunks of 8 k per CTA (144 k total)
#define CH_FL  2048          // floats per chunk tile: 128 rows * 16
#define SLAB_FL (NCHK * CH_FL)          // 36864 floats (144KB)
#define SA_FL   (2 * CH_FL)             // 4096 floats (16KB)
#define DSM_BYTES ((SLAB_FL + SA_FL) * 4)   // 163840

// -------- device globals (no allocation allowed) --------
__device__ float  g_x_hi[BATCH * SEQ * IDIM];
__device__ float  g_x_lo[BATCH * SEQ * IDIM];
__device__ float  g_wtf[8 * 8 * NCHK * 128 * 16];  // pre-formatted B slabs, 9.4MB
__device__ float  g_h_hi[BATCH * HID];
__device__ float  g_h_lo[BATCH * HID];
__device__ float4 g_part[NCTA * 8 * 16 * 32];      // 8MB partials
__device__ unsigned int g_bar;

// -------- helpers --------
static __device__ __forceinline__ float tf32f(float v) {
    float r;
    asm("cvt.rna.tf32.f32 %0, %1;" : "=f"(r) : "f"(v));
    return r;
}
static __device__ __forceinline__ void mma8(float* c,
                                            float a0, float a1, float a2, float a3,
                                            float b0, float b1) {
    asm volatile(
        "mma.sync.aligned.m16n8k8.row.col.f32.tf32.tf32.f32 "
        "{%0,%1,%2,%3},{%4,%5,%6,%7},{%8,%9},{%0,%1,%2,%3};"
        : "+f"(c[0]), "+f"(c[1]), "+f"(c[2]), "+f"(c[3])
        : "r"(__float_as_uint(a0)), "r"(__float_as_uint(a1)),
          "r"(__float_as_uint(a2)), "r"(__float_as_uint(a3)),
          "r"(__float_as_uint(b0)), "r"(__float_as_uint(b1)));
}
static __device__ __forceinline__ float my_tanh(float v) {
    float e = __expf(2.0f * v);
    return 1.0f - 2.0f / (e + 1.0f);
}
static __device__ __forceinline__ void grid_sync() {
    __syncthreads();
    if (threadIdx.x == 0) {
        __threadfence();
        unsigned ticket = atomicAdd(&g_bar, 1u);
        unsigned target = (ticket / NCTA + 1u) * NCTA;
        volatile unsigned* p = &g_bar;
        while (*p < target) { }
    }
    __syncthreads();
    __threadfence();
}

// -------- prep: split x, build pre-formatted weight slabs, zero h --------
__global__ void prep_kernel(const float* __restrict__ x,
                            const float* __restrict__ Whx,
                            const float* __restrict__ Whh) {
    const long tid = (long)blockIdx.x * blockDim.x + threadIdx.x;
    const long nt  = (long)gridDim.x * blockDim.x;
    for (long i = tid; i < (long)BATCH * SEQ * IDIM; i += nt) {
        float v = x[i];
        float h = tf32f(v);
        g_x_hi[i] = h;
        g_x_lo[i] = tf32f(v - h);
    }
    for (long i = tid; i < (long)BATCH * HID; i += nt) {
        g_h_hi[i] = 0.f;
        g_h_lo[i] = 0.f;
    }
    // weight slab rows: [tileN][ks][chunk][r], each row = 16 floats
    for (long i = tid; i < 8L * 8 * NCHK * 128; i += nt) {
        const int r  = (int)(i & 127);
        long tmp = i >> 7;
        const int c  = (int)(tmp % NCHK);
        tmp /= NCHK;
        const int ks = (int)(tmp & 7);
        const int tn = (int)(tmp >> 3);
        const int n  = tn * 128 + r;
        float* dst = g_wtf + i * 16;
        #pragma unroll
        for (int kk = 0; kk < 8; kk++) {
            const int kg = (c < 2) ? (HID + ks * 16 + c * 8 + kk)
                                   : (ks * 128 + (c - 2) * 8 + kk);
            const float w = (kg < HID) ? Whh[(long)kg * HID + n]
                                       : Whx[(long)(kg - HID) * HID + n];
            const float h = tf32f(w);
            const int p = kk & 3, q = kk >> 2;
            dst[p * 4 + q]     = h;            // hi at bytes 0..7 of slot
            dst[p * 4 + 2 + q] = tf32f(w - h); // lo at bytes 8..15
        }
    }
}

// -------- main persistent kernel --------
__global__ void __launch_bounds__(NTH, 1)
rnn_kernel(const float* __restrict__ bh,
           const float* __restrict__ Why,
           const float* __restrict__ bo,
           float* __restrict__ out) {
    extern __shared__ float dsm[];
    float* sB = dsm;              // [chunk][row][16], resident weight slab
    float* sA = dsm + SLAB_FL;    // [buf][row][16], double-buffered
    __shared__ float red[8][OUTC];

    const int tid  = threadIdx.x;
    const int bid  = blockIdx.x;
    const int wid  = tid >> 5;
    const int lane = tid & 31;

    const int tile  = bid >> 3;
    const int ks    = bid & 7;
    const int tileM = tile >> 3;
    const int tileN = tile & 7;
    const int m0    = tileM * 128;
    const int n0    = tileN * 128;

    const int wm  = wid >> 2;
    const int wn  = wid & 3;
    const int grp = lane >> 2;
    const int tig = lane & 3;

    // fragment addressing (swizzled slot layout, stride 16 floats/row)
    const int xt4      = (tig ^ ((grp >> 1) & 3)) << 2;
    const int aoffbase = (wm * 64 + grp) * 16 + xt4;
    const int boffbase = (wn * 32 + grp) * 16 + xt4;

    // A staging lanes: 2 threads per row (hi/lo planes)
    const int ar   = (tid >> 1) & 127;
    const int ap   = tid & 1;
    const int aswz = (ar >> 1) & 3;

    // ---- preload resident B slab (once) ----
    for (int i = tid; i < NCHK * 128; i += NTH) {
        const int c = i >> 7, r = i & 127;
        const float4* src = (const float4*)(g_wtf +
            ((((long)(tileN * 8 + ks) * NCHK + c) * 128 + r) * 16));
        float4 v0 = src[0], v1 = src[1], v2 = src[2], v3 = src[3];
        const int sw = (r >> 1) & 3;
        float* dst = sB + c * CH_FL + r * 16;
        *(float4*)(dst + ((0 ^ sw) << 2)) = v0;
        *(float4*)(dst + ((1 ^ sw) << 2)) = v1;
        *(float4*)(dst + ((2 ^ sw) << 2)) = v2;
        *(float4*)(dst + ((3 ^ sw) << 2)) = v3;
    }
    __syncthreads();

    // reduce-phase constants (2 iterations)
    int   r_m[2], r_n[2];
    long  r_pbase[2];
    float r_b0[2], r_b1[2];
    #pragma unroll
    for (int it = 0; it < 2; it++) {
        const int p  = ks * 16 + wid + it * 8;
        const int w  = p >> 4;
        const int qq = p & 15;
        const int wm_ = w >> 2, wn_ = w & 3;
        const int mt = qq >> 2, nt = qq & 3;
        const int gg = lane >> 2, tg = lane & 3;
        r_m[it] = m0 + wm_ * 64 + mt * 16 + gg;
        r_n[it] = n0 + wn_ * 32 + nt * 8 + tg * 2;
        r_pbase[it] = ((long)(tile * 8) * 8 + w) * 16 + qq;   // + k2*8*16 per split
        r_b0[it] = bh[r_n[it]];
        r_b1[it] = bh[r_n[it] + 1];
    }

    float acc[4][4][4];
    float4 f0, f1;

    // stage helpers
    auto ldregA = [&](int t, int c) {
        const float* src;
        if (c < 2)
            src = (ap ? g_x_lo : g_x_hi) +
                  ((long)(m0 + ar) * SEQ + t) * IDIM + ks * 16 + c * 8;
        else
            src = (ap ? g_h_lo : g_h_hi) +
                  (long)(m0 + ar) * HID + ks * 128 + (c - 2) * 8;
        f0 = *(const float4*)(src);
        f1 = *(const float4*)(src + 4);
    };
    auto stsA = [&](int buf) {
        float fa[8];
        *(float4*)(fa)     = f0;
        *(float4*)(fa + 4) = f1;
        float* dst = sA + buf * CH_FL + ar * 16 + ap * 2;
        #pragma unroll
        for (int p = 0; p < 4; p++)
            *(float2*)(dst + ((p ^ aswz) << 2)) = make_float2(fa[p], fa[p + 4]);
    };
    auto compute = [&](int c, int buf) {
        float4 aF[4][2];
        const float* ab = sA + buf * CH_FL + aoffbase;
        #pragma unroll
        for (int mt = 0; mt < 4; mt++) {
            aF[mt][0] = *(const float4*)(ab + mt * 256);
            aF[mt][1] = *(const float4*)(ab + mt * 256 + 128);
        }
        const float* bb = sB + c * CH_FL + boffbase;
        #pragma unroll
        for (int nt = 0; nt < 4; nt++) {
            float4 b = *(const float4*)(bb + nt * 128);
            #pragma unroll
            for (int mt = 0; mt < 4; mt++) {
                mma8(acc[mt][nt], aF[mt][0].x, aF[mt][1].x, aF[mt][0].y, aF[mt][1].y, b.x, b.y);
                mma8(acc[mt][nt], aF[mt][0].x, aF[mt][1].x, aF[mt][0].y, aF[mt][1].y, b.z, b.w);
                mma8(acc[mt][nt], aF[mt][0].z, aF[mt][1].z, aF[mt][0].w, aF[mt][1].w, b.x, b.y);
            }
        }
    };

    for (int t = 0; t < SEQ; t++) {
        #pragma unroll
        for (int mt = 0; mt < 4; mt++)
            #pragma unroll
            for (int nt = 0; nt < 4; nt++)
                #pragma unroll
                for (int cc = 0; cc < 4; cc++)
                    acc[mt][nt][cc] = 0.f;

        // ---- x chunks (0,1): h-independent, run before the grid barrier ----
        ldregA(t, 0); stsA(0); __syncthreads();
        ldregA(t, 1); compute(0, 0); stsA(1); __syncthreads();
        compute(1, 1);

        grid_sync();   // h_t from previous reduce now visible everywhere

        // ---- h chunks (2..17) ----
        ldregA(t, 2); stsA(0); __syncthreads();
        #pragma unroll 1
        for (int c = 2; c < NCHK - 1; c++) {
            ldregA(t, c + 1);
            compute(c, c & 1);
            stsA((c + 1) & 1);
            __syncthreads();
        }
        compute(NCHK - 1, (NCHK - 1) & 1);

        // ---- store partials ----
        {
            float4* pp = g_part + ((long)(bid * 8 + wid) * 16) * 32 + lane;
            #pragma unroll
            for (int mt = 0; mt < 4; mt++)
                #pragma unroll
                for (int nt = 0; nt < 4; nt++) {
                    const int q = mt * 4 + nt;
                    pp[q * 32] = make_float4(acc[mt][nt][0], acc[mt][nt][1],
                                             acc[mt][nt][2], acc[mt][nt][3]);
                }
        }
        grid_sync();

        // ---- reduce: sum 8 K-splits, bias+tanh, write split h ----
        #pragma unroll
        for (int it = 0; it < 2; it++) {
            float s0 = 0.f, s1 = 0.f, s2 = 0.f, s3 = 0.f;
            #pragma unroll
            for (int k2 = 0; k2 < 8; k2++) {
                float4 v = g_part[(r_pbase[it] + (long)k2 * 8 * 16) * 32 + lane];
                s0 += v.x; s1 += v.y; s2 += v.z; s3 += v.w;
            }
            const float t0 = my_tanh(s0 + r_b0[it]);
            const float t1 = my_tanh(s1 + r_b1[it]);
            const float t2 = my_tanh(s2 + r_b0[it]);
            const float t3 = my_tanh(s3 + r_b1[it]);
            const float h0 = tf32f(t0), h1 = tf32f(t1), h2 = tf32f(t2), h3 = tf32f(t3);
            const long o0 = (long)r_m[it] * HID + r_n[it];
            const long o1 = (long)(r_m[it] + 8) * HID + r_n[it];
            *(float2*)(g_h_hi + o0) = make_float2(h0, h1);
            *(float2*)(g_h_hi + o1) = make_float2(h2, h3);
            *(float2*)(g_h_lo + o0) = make_float2(tf32f(t0 - h0), tf32f(t1 - h1));
            *(float2*)(g_h_lo + o1) = make_float2(tf32f(t2 - h2), tf32f(t3 - h3));
        }
    }

    grid_sync();   // final h visible

    // ---- classifier + softmax: 2 rows per CTA ----
    for (int rr = 0; rr < 2; rr++) {
        const int row = bid * 2 + rr;
        float a[OUTC];
        #pragma unroll
        for (int o = 0; o < OUTC; o++) a[o] = 0.f;
        for (int k = tid; k < HID; k += NTH) {
            const float hv = g_h_hi[(long)row * HID + k] + g_h_lo[(long)row * HID + k];
            const float* wr = Why + (long)k * OUTC;
            #pragma unroll
            for (int o = 0; o < OUTC; o++) a[o] += hv * wr[o];
        }
        #pragma unroll
        for (int o = 0; o < OUTC; o++)
            #pragma unroll
            for (int off = 16; off > 0; off >>= 1)
                a[o] += __shfl_down_sync(0xffffffffu, a[o], off);
        if (lane == 0) {
            #pragma unroll
            for (int o = 0; o < OUTC; o++) red[wid][o] = a[o];
        }
        __syncthreads();
        if (tid == 0) {
            float v[OUTC];
            float mx = -1e30f;
            #pragma unroll
            for (int o = 0; o < OUTC; o++) {
                float s8 = 0.f;
                #pragma unroll
                for (int w = 0; w < 8; w++) s8 += red[w][o];
                v[o] = s8 + bo[o];
                mx = fmaxf(mx, v[o]);
            }
            float s = 0.f;
            #pragma unroll
            for (int o = 0; o < OUTC; o++) { v[o] = expf(v[o] - mx); s += v[o]; }
            const float inv = 1.0f / s;
            #pragma unroll
            for (int o = 0; o < OUTC; o++) out[row * OUTC + o] = v[o] * inv;
        }
        __syncthreads();
    }
}

extern "C" void kernel_launch(void* const* d_in, const int* in_sizes, int n_in,
                              void* d_out, int out_size) {
    const float* x   = (const float*)d_in[0];
    const float* Whx = (const float*)d_in[1];
    const float* Whh = (const float*)d_in[2];
    const float* bh  = (const float*)d_in[3];
    const float* Why = (const float*)d_in[4];
    const float* bo  = (const float*)d_in[5];
    float* out = (float*)d_out;

    static int attr_done = 0;
    if (!attr_done) {
        cudaFuncSetAttribute(rnn_kernel,
                             cudaFuncAttributeMaxDynamicSharedMemorySize,
                             DSM_BYTES);
        attr_done = 1;
    }
    prep_kernel<<<1024, 256>>>(x, Whx, Whh);
    rnn_kernel<<<NCTA, NTH, DSM_BYTES>>>(bh, Why, bo, out);
}

// round 7
// speedup vs baseline: 1.6709x; 1.6709x over previous
#include <cuda_runtime.h>
#include <cuda_bf16.h>
#include <stdint.h>
#include <math.h>

#define BATCH 256
#define SEQ   256
#define IDIM  128
#define HID   1024
#define OUTC  10

#define NCTA  128
#define NTH   256
#define CHK   9                    // k16 chunks per CTA (1 x-chunk + 8 h-chunks)
#define CHW   2048                 // uint32 words per chunk tile (128 rows * 16)
#define DSMW  ((CHK + 2) * CHW)    // B slab (9) + A double buffer (2)
#define DSMB  (DSMW * 4)           // 90112 bytes

// -------- device globals (no allocation allowed) --------
__device__ uint32_t g_xs[BATCH * SEQ * 8 * 16];      // packed x slots, 33.5MB
__device__ uint32_t g_bs[8 * 8 * CHK * 128 * 16];    // packed W slabs, 4.5MB
__device__ uint32_t g_hs[BATCH * 64 * 16];           // packed h slots, 1MB
__device__ float    g_h[BATCH * HID];                // plain h (last step only)
__device__ float4   g_part[NCTA * 8 * 16 * 32];      // partials, 8MB
__device__ unsigned int g_bar;

// -------- helpers --------
static __device__ __forceinline__ uint32_t pk2(float a, float b) {
    __nv_bfloat162 t = __floats2bfloat162_rn(a, b);   // low = a, high = b
    return *reinterpret_cast<uint32_t*>(&t);
}
static __device__ __forceinline__ float bf16rt(float v) {
    return __bfloat162float(__float2bfloat16_rn(v));
}
// slot layout per (row, k16 group): 4 slots of 16B, slot t =
//   { hi(k2t,k2t+1), hi(k2t+8,k2t+9), lo(k2t,k2t+1), lo(k2t+8,k2t+9) }
static __device__ __forceinline__ void pack16(const float* v, uint4* dst) {
    #pragma unroll
    for (int t = 0; t < 4; t++) {
        const float a0 = v[2*t],   a1 = v[2*t+1];
        const float a8 = v[2*t+8], a9 = v[2*t+9];
        uint4 s;
        s.x = pk2(a0, a1);
        s.y = pk2(a8, a9);
        s.z = pk2(a0 - bf16rt(a0), a1 - bf16rt(a1));
        s.w = pk2(a8 - bf16rt(a8), a9 - bf16rt(a9));
        dst[t] = s;
    }
}
static __device__ __forceinline__ void mma16(float* c,
        uint32_t a0, uint32_t a1, uint32_t a2, uint32_t a3,
        uint32_t b0, uint32_t b1) {
    asm volatile(
        "mma.sync.aligned.m16n8k16.row.col.f32.bf16.bf16.f32 "
        "{%0,%1,%2,%3},{%4,%5,%6,%7},{%8,%9},{%0,%1,%2,%3};"
        : "+f"(c[0]), "+f"(c[1]), "+f"(c[2]), "+f"(c[3])
        : "r"(a0), "r"(a1), "r"(a2), "r"(a3), "r"(b0), "r"(b1));
}
static __device__ __forceinline__ float my_tanh(float v) {
    float e = __expf(2.0f * v);
    return 1.0f - 2.0f / (e + 1.0f);
}
static __device__ __forceinline__ void grid_sync() {
    __syncthreads();
    if (threadIdx.x == 0) {
        __threadfence();
        unsigned ticket = atomicAdd(&g_bar, 1u);
        unsigned target = (ticket / NCTA + 1u) * NCTA;
        volatile unsigned* p = &g_bar;
        while (*p < target) { }
    }
    __syncthreads();
    __threadfence();
}

// -------- prep: pack x & W into slot layout, zero h --------
__global__ void prep_kernel(const float* __restrict__ x,
                            const float* __restrict__ Whx,
                            const float* __restrict__ Whh) {
    const long tid = (long)blockIdx.x * blockDim.x + threadIdx.x;
    const long nt  = (long)gridDim.x * blockDim.x;
    // x: one thread per (b*t, g) group of 16
    for (long i = tid; i < (long)BATCH * SEQ * 8; i += nt) {
        const long bt = i >> 3;
        const int  g  = (int)(i & 7);
        const float* src = x + bt * IDIM + g * 16;
        float v[16];
        #pragma unroll
        for (int j = 0; j < 16; j++) v[j] = src[j];
        pack16(v, (uint4*)(g_xs + i * 16));
    }
    // W: one thread per (tn, ks, c, col)
    for (long i = tid; i < 8L * 8 * CHK * 128; i += nt) {
        const int col = (int)(i & 127);
        long tmp = i >> 7;
        const int c  = (int)(tmp % CHK); tmp /= CHK;
        const int ks = (int)(tmp & 7);
        const int tn = (int)(tmp >> 3);
        const int n  = tn * 128 + col;
        const int kbase = (c == 0) ? (HID + ks * 16) : (ks * 128 + (c - 1) * 16);
        float v[16];
        #pragma unroll
        for (int j = 0; j < 16; j++) {
            const int k = kbase + j;
            v[j] = (k < HID) ? Whh[(long)k * HID + n] : Whx[(long)(k - HID) * HID + n];
        }
        pack16(v, (uint4*)(g_bs + i * 16));
    }
    for (long i = tid; i < (long)BATCH * 64 * 16; i += nt) g_hs[i] = 0u;
    for (long i = tid; i < (long)BATCH * HID; i += nt)     g_h[i]  = 0.f;
}

// -------- main persistent kernel --------
__global__ void __launch_bounds__(NTH, 1)
rnn_kernel(const float* __restrict__ bh,
           const float* __restrict__ Why,
           const float* __restrict__ bo,
           float* __restrict__ out) {
    extern __shared__ uint32_t dsm[];
    uint32_t* sB = dsm;              // [chunk][row][16 words], resident slab
    uint32_t* sA = dsm + CHK * CHW;  // [buf][row][16 words]
    __shared__ float red[8][OUTC];

    const int tid  = threadIdx.x;
    const int bid  = blockIdx.x;
    const int wid  = tid >> 5;
    const int lane = tid & 31;

    const int tile  = bid >> 3;
    const int ks    = bid & 7;
    const int tileM = tile >> 3;
    const int tileN = tile & 7;
    const int m0    = tileM * 128;
    const int n0    = tileN * 128;

    const int wm  = wid >> 2;
    const int wn  = wid & 3;
    const int grp = lane >> 2;
    const int tig = lane & 3;

    // A staging lanes: 2 threads per row
    const int r    = tid >> 1;
    const int half = tid & 1;

    // fragment smem offsets (uint32 words)
    const int aoff = (wm * 64 + grp) * 16 + tig * 4;
    const int boff = (wn * 32 + grp) * 16 + tig * 4;

    // ---- preload resident B slab ----
    {
        const uint4* src = (const uint4*)(g_bs + (long)(tileN * 8 + ks) * CHK * CHW);
        uint4* dst = (uint4*)sB;
        for (int i = tid; i < CHK * 512; i += NTH) dst[i] = src[i];
    }
    __syncthreads();

    // reduce-phase constants
    int   r_m[2], r_n[2], r_hoff[2];
    long  r_pbase[2];
    float r_b0[2], r_b1[2];
    #pragma unroll
    for (int it = 0; it < 2; it++) {
        const int p  = ks * 16 + wid + it * 8;
        const int w  = p >> 4;
        const int qq = p & 15;
        const int wm_ = w >> 2, wn_ = w & 3;
        const int mt = qq >> 2, nt = qq & 3;
        r_m[it] = m0 + wm_ * 64 + mt * 16 + (lane >> 2);
        r_n[it] = n0 + wn_ * 32 + nt * 8 + (lane & 3) * 2;
        r_pbase[it] = ((long)(tile * 8) * 8 + w) * 16 + qq;
        r_b0[it] = bh[r_n[it]];
        r_b1[it] = bh[r_n[it] + 1];
        const int j = r_n[it] & 15;
        r_hoff[it] = (r_m[it] * 64 + (r_n[it] >> 4)) * 16 +
                     ((j < 8) ? (j >> 1) * 4 : ((j - 8) >> 1) * 4 + 1);
    }

    float acc[4][4][4];
    uint4 u0, u1;

    auto ldgA = [&](int c, int t) {
        const uint32_t* src = (c == 0)
            ? g_xs + (((long)(m0 + r) * SEQ + t) * 8 + ks) * 16 + half * 8
            : g_hs + ((long)(m0 + r) * 64 + ks * 8 + (c - 1)) * 16 + half * 8;
        u0 = *(const uint4*)(src);
        u1 = *(const uint4*)(src + 4);
    };
    auto stsA = [&](int buf) {
        uint4* d = (uint4*)(sA + buf * CHW + r * 16 + half * 8);
        d[0] = u0;
        d[1] = u1;
    };
    auto compute = [&](int c, int buf) {
        const uint32_t* ab = sA + buf * CHW + aoff;
        uint4 ra[4][2];
        #pragma unroll
        for (int mt = 0; mt < 4; mt++) {
            ra[mt][0] = *(const uint4*)(ab + mt * 256);         // rows grp
            ra[mt][1] = *(const uint4*)(ab + mt * 256 + 128);   // rows grp+8
        }
        const uint32_t* bb = sB + c * CHW + boff;
        #pragma unroll
        for (int nt = 0; nt < 4; nt++) {
            const uint4 bv = *(const uint4*)(bb + nt * 128);
            #pragma unroll
            for (int mt = 0; mt < 4; mt++) {
                // aH*bH, aH*bL, aL*bH
                mma16(acc[mt][nt], ra[mt][0].x, ra[mt][1].x, ra[mt][0].y, ra[mt][1].y, bv.x, bv.y);
                mma16(acc[mt][nt], ra[mt][0].x, ra[mt][1].x, ra[mt][0].y, ra[mt][1].y, bv.z, bv.w);
                mma16(acc[mt][nt], ra[mt][0].z, ra[mt][1].z, ra[mt][0].w, ra[mt][1].w, bv.x, bv.y);
            }
        }
    };

    for (int t = 0; t < SEQ; t++) {
        #pragma unroll
        for (int mt = 0; mt < 4; mt++)
            #pragma unroll
            for (int nt = 0; nt < 4; nt++)
                #pragma unroll
                for (int cc = 0; cc < 4; cc++)
                    acc[mt][nt][cc] = 0.f;

        // ---- x chunk (h-independent): runs before the grid barrier ----
        ldgA(0, t);
        stsA(0);
        __syncthreads();
        compute(0, 0);

        grid_sync();   // h_t from previous reduce now visible

        // ---- h chunks 1..8, double-buffered ----
        ldgA(1, t);
        stsA(1);
        __syncthreads();
        #pragma unroll 1
        for (int c = 1; c < CHK; c++) {
            if (c + 1 < CHK) ldgA(c + 1, t);
            compute(c, c & 1);
            if (c + 1 < CHK) stsA((c + 1) & 1);
            __syncthreads();
        }

        // ---- store partials ----
        {
            float4* pp = g_part + ((long)(bid * 8 + wid) * 16) * 32 + lane;
            #pragma unroll
            for (int mt = 0; mt < 4; mt++)
                #pragma unroll
                for (int nt = 0; nt < 4; nt++) {
                    const int q = mt * 4 + nt;
                    pp[q * 32] = make_float4(acc[mt][nt][0], acc[mt][nt][1],
                                             acc[mt][nt][2], acc[mt][nt][3]);
                }
        }
        grid_sync();

        // ---- reduce: sum 8 K-splits, bias+tanh, write packed h ----
        #pragma unroll
        for (int it = 0; it < 2; it++) {
            float s0 = 0.f, s1 = 0.f, s2 = 0.f, s3 = 0.f;
            #pragma unroll
            for (int k2 = 0; k2 < 8; k2++) {
                float4 v = g_part[(r_pbase[it] + (long)k2 * 128) * 32 + lane];
                s0 += v.x; s1 += v.y; s2 += v.z; s3 += v.w;
            }
            const float t0 = my_tanh(s0 + r_b0[it]);
            const float t1 = my_tanh(s1 + r_b1[it]);
            const float t2 = my_tanh(s2 + r_b0[it]);
            const float t3 = my_tanh(s3 + r_b1[it]);
            const float f0 = bf16rt(t0), f1 = bf16rt(t1);
            const float f2 = bf16rt(t2), f3 = bf16rt(t3);
            // row r_m
            g_hs[r_hoff[it]]     = pk2(t0, t1);
            g_hs[r_hoff[it] + 2] = pk2(t0 - f0, t1 - f1);
            // row r_m + 8  (+8 rows = +8192 words)
            g_hs[r_hoff[it] + 8192]     = pk2(t2, t3);
            g_hs[r_hoff[it] + 8192 + 2] = pk2(t2 - f2, t3 - f3);
            if (t == SEQ - 1) {
                g_h[(long)r_m[it] * HID + r_n[it]]           = t0;
                g_h[(long)r_m[it] * HID + r_n[it] + 1]       = t1;
                g_h[(long)(r_m[it] + 8) * HID + r_n[it]]     = t2;
                g_h[(long)(r_m[it] + 8) * HID + r_n[it] + 1] = t3;
            }
        }
    }

    grid_sync();   // final h visible

    // ---- classifier + softmax: 2 rows per CTA ----
    for (int rr = 0; rr < 2; rr++) {
        const int row = bid * 2 + rr;
        float a[OUTC];
        #pragma unroll
        for (int o = 0; o < OUTC; o++) a[o] = 0.f;
        for (int k = tid; k < HID; k += NTH) {
            const float hv = g_h[(long)row * HID + k];
            const float* wr = Why + (long)k * OUTC;
            #pragma unroll
            for (int o = 0; o < OUTC; o++) a[o] += hv * wr[o];
        }
        #pragma unroll
        for (int o = 0; o < OUTC; o++)
            #pragma unroll
            for (int off = 16; off > 0; off >>= 1)
                a[o] += __shfl_down_sync(0xffffffffu, a[o], off);
        if (lane == 0) {
            #pragma unroll
            for (int o = 0; o < OUTC; o++) red[wid][o] = a[o];
        }
        __syncthreads();
        if (tid == 0) {
            float v[OUTC];
            float mx = -1e30f;
            #pragma unroll
            for (int o = 0; o < OUTC; o++) {
                float s8 = 0.f;
                #pragma unroll
                for (int w = 0; w < 8; w++) s8 += red[w][o];
                v[o] = s8 + bo[o];
                mx = fmaxf(mx, v[o]);
            }
            float s = 0.f;
            #pragma unroll
            for (int o = 0; o < OUTC; o++) { v[o] = expf(v[o] - mx); s += v[o]; }
            const float inv = 1.0f / s;
            #pragma unroll
            for (int o = 0; o < OUTC; o++) out[row * OUTC + o] = v[o] * inv;
        }
        __syncthreads();
    }
}

extern "C" void kernel_launch(void* const* d_in, const int* in_sizes, int n_in,
                              void* d_out, int out_size) {
    const float* x   = (const float*)d_in[0];
    const float* Whx = (const float*)d_in[1];
    const float* Whh = (const float*)d_in[2];
    const float* bh  = (const float*)d_in[3];
    const float* Why = (const float*)d_in[4];
    const float* bo  = (const float*)d_in[5];
    float* out = (float*)d_out;

    static int attr_done = 0;
    if (!attr_done) {
        cudaFuncSetAttribute(rnn_kernel,
                             cudaFuncAttributeMaxDynamicSharedMemorySize,
                             DSMB);
        attr_done = 1;
    }
    prep_kernel<<<1024, 256>>>(x, Whx, Whh);
    rnn_kernel<<<NCTA, NTH, DSMB>>>(bh, Why, bo, out);
}